// round 8
// baseline (speedup 1.0000x reference)
#include <cuda_runtime.h>

#define KCLS 19
#define NIMG 4
#define CDIM 128
#define PPIX 131072   // 256*512

// Scratch (device globals; no allocation allowed)
__device__ unsigned char g_lab[NIMG * PPIX];
__device__ float g_sums[NIMG * KCLS * CDIM];
__device__ int   g_cnt[NIMG * 20];
__device__ float g_rsum[NIMG * KCLS];
__device__ float g_mt[NIMG * CDIM * KCLS];   // means transposed [n][c][k]
__device__ int   g_is64;                      // 1 if target buffer is int64

// ---------------------------------------------------------------------------
// Detect target dtype. int64 labels < 19 => every odd int32 word is 0.
// Reads only the first 2 KiB (in-bounds for both int32 and int64 layouts).
// ---------------------------------------------------------------------------
__global__ void k_detect(const int* __restrict__ t32) {
    __shared__ int bad;
    if (threadIdx.x == 0) bad = 0;
    __syncthreads();
    int w = t32[threadIdx.x * 2 + 1];   // odd words 1,3,...,511
    if (w != 0) atomicOr(&bad, 1);
    __syncthreads();
    if (threadIdx.x == 0) g_is64 = bad ? 0 : 1;
}

// ---------------------------------------------------------------------------
// Zero accumulators
// ---------------------------------------------------------------------------
__global__ void k_init() {
    int i = blockIdx.x * blockDim.x + threadIdx.x;
    if (i < NIMG * KCLS * CDIM) g_sums[i] = 0.f;
    if (i < NIMG * 20)          g_cnt[i] = 0;
    if (i < NIMG * KCLS)        g_rsum[i] = 0.f;
}

// ---------------------------------------------------------------------------
// Convert labels (int64 OR int32, per g_is64) -> u8, histogram counts.
// grid (32, NIMG), 256 threads; each block handles 4096 pixels.
// ---------------------------------------------------------------------------
__global__ void k_prep(const void* __restrict__ tgt) {
    int n = blockIdx.y;
    int tid = threadIdx.x;
    __shared__ int h[20];
    if (tid < 20) h[tid] = 0;
    __syncthreads();

    unsigned char* lp = g_lab + (size_t)n * PPIX;
    const int is64 = g_is64;

    #pragma unroll
    for (int it = 0; it < 4; ++it) {
        int p = blockIdx.x * 4096 + it * 1024 + tid * 4;
        int v0, v1, v2, v3;
        if (is64) {
            const long long* tp = (const long long*)tgt + (size_t)n * PPIX;
            longlong2 a = *(const longlong2*)(tp + p);
            longlong2 b = *(const longlong2*)(tp + p + 2);
            v0 = (int)a.x; v1 = (int)a.y; v2 = (int)b.x; v3 = (int)b.y;
        } else {
            const int* tp = (const int*)tgt + (size_t)n * PPIX;
            int4 a = *(const int4*)(tp + p);
            v0 = a.x; v1 = a.y; v2 = a.z; v3 = a.w;
        }
        uchar4 u;
        u.x = (v0 >= 0 && v0 < KCLS) ? (unsigned char)v0 : (unsigned char)255;
        u.y = (v1 >= 0 && v1 < KCLS) ? (unsigned char)v1 : (unsigned char)255;
        u.z = (v2 >= 0 && v2 < KCLS) ? (unsigned char)v2 : (unsigned char)255;
        u.w = (v3 >= 0 && v3 < KCLS) ? (unsigned char)v3 : (unsigned char)255;
        *(uchar4*)(lp + p) = u;
        atomicAdd(&h[u.x < KCLS ? (int)u.x : 19], 1);
        atomicAdd(&h[u.y < KCLS ? (int)u.y : 19], 1);
        atomicAdd(&h[u.z < KCLS ? (int)u.z : 19], 1);
        atomicAdd(&h[u.w < KCLS ? (int)u.w : 19], 1);
    }
    __syncthreads();
    if (tid < 20) atomicAdd(&g_cnt[n * 20 + tid], h[tid]);
}

// ---------------------------------------------------------------------------
// Pass 1: segment sums.  grid (8, CDIM, NIMG), 256 threads.
// Block owns one channel, 16384-pixel chunk. Privatized smem acc [20][256].
// ---------------------------------------------------------------------------
__global__ void k_segsum(const float* __restrict__ x) {
    const int CH = 16384;
    int n = blockIdx.z, c = blockIdx.y, chunk = blockIdx.x;
    int tid = threadIdx.x;

    __shared__ float acc[20 * 256];
    #pragma unroll
    for (int k = 0; k < 20; ++k) acc[k * 256 + tid] = 0.f;
    __syncthreads();

    const float4* xp = (const float4*)(x + ((size_t)(n * CDIM + c)) * PPIX + (size_t)chunk * CH);
    const uchar4* lp = (const uchar4*)(g_lab + (size_t)n * PPIX + (size_t)chunk * CH);

    #pragma unroll 4
    for (int i = tid; i < CH / 4; i += 256) {
        float4 v = xp[i];
        uchar4 l = lp[i];
        int k0 = l.x < KCLS ? (int)l.x : 19;
        int k1 = l.y < KCLS ? (int)l.y : 19;
        int k2 = l.z < KCLS ? (int)l.z : 19;
        int k3 = l.w < KCLS ? (int)l.w : 19;
        acc[k0 * 256 + tid] += v.x;
        acc[k1 * 256 + tid] += v.y;
        acc[k2 * 256 + tid] += v.z;
        acc[k3 * 256 + tid] += v.w;
    }
    __syncthreads();

    int warp = tid >> 5, lane = tid & 31;
    for (int k = warp; k < KCLS; k += 8) {
        float s = 0.f;
        #pragma unroll
        for (int j = 0; j < 8; ++j) s += acc[k * 256 + j * 32 + lane];
        #pragma unroll
        for (int o = 16; o > 0; o >>= 1) s += __shfl_down_sync(0xffffffffu, s, o);
        if (lane == 0) atomicAdd(&g_sums[(n * KCLS + k) * CDIM + c], s);
    }
}

// ---------------------------------------------------------------------------
// Means (transposed [n][c][k] for conflict-free LDS in pass 2)
// ---------------------------------------------------------------------------
__global__ void k_means() {
    int i = blockIdx.x * 256 + threadIdx.x;
    if (i >= NIMG * KCLS * CDIM) return;
    int n = i / (KCLS * CDIM);
    int k = (i / CDIM) % KCLS;
    int c = i % CDIM;
    float cnt = fmaxf((float)g_cnt[n * 20 + k], 1.f);
    g_mt[(n * CDIM + c) * KCLS + k] = g_sums[i] / cnt;
}

// ---------------------------------------------------------------------------
// Pass 2: per-pixel distance to class mean, relu margin, per-class sums.
// grid (256, NIMG), 256 threads; block covers 512 pixels (2/thread).
// ---------------------------------------------------------------------------
__global__ void k_var(const float* __restrict__ x) {
    int n = blockIdx.y;
    int tid = threadIdx.x;
    __shared__ float ms[CDIM * KCLS];   // 2432 floats
    __shared__ float rpart[KCLS];

    for (int i = tid; i < CDIM * KCLS; i += 256) ms[i] = g_mt[n * CDIM * KCLS + i];
    if (tid < KCLS) rpart[tid] = 0.f;
    __syncthreads();

    int p0 = blockIdx.x * 512 + tid * 2;
    int l0 = g_lab[(size_t)n * PPIX + p0];
    int l1 = g_lab[(size_t)n * PPIX + p0 + 1];
    int b0 = l0 < KCLS ? l0 : 0;
    int b1 = l1 < KCLS ? l1 : 0;

    const float* xp = x + ((size_t)n * CDIM) * PPIX + p0;
    float a0 = 0.f, a1 = 0.f;

    #pragma unroll 8
    for (int c = 0; c < CDIM; ++c) {
        float2 v = *(const float2*)(xp + (size_t)c * PPIX);
        float m0 = ms[c * KCLS + b0];
        float m1 = ms[c * KCLS + b1];
        float t0 = m0 - v.x, t1 = m1 - v.y;
        a0 = fmaf(t0, t0, a0);
        a1 = fmaf(t1, t1, a1);
    }

    float r0 = fmaxf(sqrtf(a0) - 0.5f, 0.f); r0 *= r0;
    float r1 = fmaxf(sqrtf(a1) - 0.5f, 0.f); r1 *= r1;
    if (l0 < KCLS) atomicAdd(&rpart[l0], r0);
    if (l1 < KCLS) atomicAdd(&rpart[l1], r1);
    __syncthreads();
    if (tid < KCLS) atomicAdd(&g_rsum[n * KCLS + tid], rpart[tid]);
}

// ---------------------------------------------------------------------------
// Final scalar: loss_var + loss_dis + 0.001 * loss_reg, mean over images.
// 1 block, 512 threads. Means in smem padded to stride 129 (bank-safe).
// ---------------------------------------------------------------------------
__global__ void k_final(float* __restrict__ out) {
    __shared__ float m[KCLS * 129];
    __shared__ float s_var, s_dis, s_reg;
    int tid = threadIdx.x;
    float total = 0.f;   // meaningful on tid 0 only

    for (int n = 0; n < NIMG; ++n) {
        if (tid == 0) { s_var = 0.f; s_dis = 0.f; s_reg = 0.f; }
        __syncthreads();

        for (int i = tid; i < KCLS * CDIM; i += 512) {
            int k = i / CDIM, c = i % CDIM;
            float cnt = fmaxf((float)g_cnt[n * 20 + k], 1.f);
            m[k * 129 + c] = g_sums[(n * KCLS + k) * CDIM + c] / cnt;
        }
        __syncthreads();

        if (tid < KCLS) {
            int cnt = g_cnt[n * 20 + tid];
            if (cnt > 20) {
                atomicAdd(&s_var, g_rsum[n * KCLS + tid] / (float)cnt);
                float nr = 0.f;
                #pragma unroll 4
                for (int c = 0; c < CDIM; ++c) {
                    float mv = m[tid * 129 + c];
                    nr = fmaf(mv, mv, nr);
                }
                atomicAdd(&s_reg, sqrtf(nr));
            }
        }
        if (tid < KCLS * KCLS) {
            int f = tid / KCLS, s = tid % KCLS;
            if (f != s && g_cnt[n * 20 + f] > 20 && g_cnt[n * 20 + s] > 20) {
                float d2 = 0.f;
                #pragma unroll 4
                for (int c = 0; c < CDIM; ++c) {
                    float d = m[f * 129 + c] - m[s * 129 + c];
                    d2 = fmaf(d, d, d2);
                }
                float t = fmaxf(3.0f - sqrtf(d2), 0.f);   // 2*DELTA = 3.0
                atomicAdd(&s_dis, t * t);
            }
        }
        __syncthreads();

        if (tid == 0) {
            int nvi = 0;
            for (int k = 0; k < KCLS; ++k) nvi += (g_cnt[n * 20 + k] > 20);
            float nv = fmaxf((float)nvi, 1.f);
            float connect = fmaxf(nv * (nv - 1.f), 1.f);
            total += s_var / nv + s_dis / connect + 0.001f * s_reg / nv;
        }
        __syncthreads();
    }
    if (tid == 0) out[0] = total * 0.25f;
}

// ---------------------------------------------------------------------------
extern "C" void kernel_launch(void* const* d_in, const int* in_sizes, int n_in,
                              void* d_out, int out_size) {
    int pi = 0, ti = 1;
    if (n_in >= 2 && in_sizes[0] == NIMG * PPIX) { pi = 1; ti = 0; }  // robustness vs input order
    const float* predict = (const float*)d_in[pi];
    const void* target = (const void*)d_in[ti];
    float* out = (float*)d_out;

    k_detect<<<1, 256>>>((const int*)target);
    k_init<<<(NIMG * KCLS * CDIM + 255) / 256, 256>>>();
    k_prep<<<dim3(PPIX / 4096, NIMG), 256>>>(target);
    k_segsum<<<dim3(PPIX / 16384, CDIM, NIMG), 256>>>(predict);
    k_means<<<(NIMG * KCLS * CDIM + 255) / 256, 256>>>();
    k_var<<<dim3(PPIX / 512, NIMG), 256>>>(predict);
    k_final<<<1, 512>>>(out);
}